// round 13
// baseline (speedup 1.0000x reference)
#include <cuda_runtime.h>

#define KNN      11
#define NPTS     50000
#define NSP      4000
#define NB       2
#define G        20
#define NCELL    (G*G*G)                  // 8000
#define CHUNK    ((NCELL + 255) / 256)    // 32
#define TMAIN    512
#define BLKS_MAIN ((NPTS + TMAIN - 1) / TMAIN)
#define SENT     0x7FFFFFFF

// ---------------- device scratch (no allocations allowed) ----------------
__device__ float4         g_spk[NB][NSP];       // cell-sorted sites, w = int_as_float(sidx<<12)
__device__ unsigned short g_cst[NB][NCELL + 1]; // site cell start offsets
__device__ float          g_box[NB][9];         // mn[3], h[3], inv_h[3]
__device__ int            g_pcnt[NB][NCELL];
__device__ int            g_pcur[NB][NCELL];
__device__ float4         g_pts[NB][NPTS];      // cell-sorted queries (w = orig idx)

__device__ __forceinline__ int cell_of(float x, float y, float z, const float* bx) {
    int cx = (int)((x - bx[0]) * bx[6]); cx = min(G - 1, max(0, cx));
    int cy = (int)((y - bx[1]) * bx[7]); cy = min(G - 1, max(0, cy));
    int cz = (int)((z - bx[2]) * bx[8]); cz = min(G - 1, max(0, cz));
    return (cx * G + cy) * G + cz;
}

// ---------------- kernel 1: bin sites into grid (one block per batch) ----------------
static constexpr int SM_SETUP = (NCELL + NCELL + 1 + 256) * 4 + 48 * 4;

__global__ void k_setup_sites(const float* __restrict__ spoints) {
    extern __shared__ int sm[];
    int*   cnt = sm;                  // NCELL
    int*   st  = cnt + NCELL;         // NCELL+1
    int*   tot = st + NCELL + 1;      // 256
    float* red = (float*)(tot + 256); // 48
    __shared__ float sbox[9];

    const int b = blockIdx.x, tid = threadIdx.x;
    const float* sp = spoints + (size_t)b * NSP * 3;

    for (int c = tid; c < NCELL; c += blockDim.x) g_pcnt[b][c] = 0;

    float mnx = 3e38f, mny = 3e38f, mnz = 3e38f;
    float mxx = -3e38f, mxy = -3e38f, mxz = -3e38f;
    for (int i = tid; i < NSP; i += blockDim.x) {
        float x = sp[3*i], y = sp[3*i+1], z = sp[3*i+2];
        mnx = fminf(mnx, x); mxx = fmaxf(mxx, x);
        mny = fminf(mny, y); mxy = fmaxf(mxy, y);
        mnz = fminf(mnz, z); mxz = fmaxf(mxz, z);
    }
#pragma unroll
    for (int o = 16; o; o >>= 1) {
        mnx = fminf(mnx, __shfl_xor_sync(0xffffffffu, mnx, o));
        mny = fminf(mny, __shfl_xor_sync(0xffffffffu, mny, o));
        mnz = fminf(mnz, __shfl_xor_sync(0xffffffffu, mnz, o));
        mxx = fmaxf(mxx, __shfl_xor_sync(0xffffffffu, mxx, o));
        mxy = fmaxf(mxy, __shfl_xor_sync(0xffffffffu, mxy, o));
        mxz = fmaxf(mxz, __shfl_xor_sync(0xffffffffu, mxz, o));
    }
    int w = tid >> 5;
    if ((tid & 31) == 0) {
        red[w] = mnx; red[8 + w] = mny; red[16 + w] = mnz;
        red[24 + w] = mxx; red[32 + w] = mxy; red[40 + w] = mxz;
    }
    __syncthreads();
    if (tid == 0) {
        float a0 = red[0], a1 = red[8], a2 = red[16], a3 = red[24], a4 = red[32], a5 = red[40];
        for (int i = 1; i < 8; i++) {
            a0 = fminf(a0, red[i]);      a1 = fminf(a1, red[8 + i]);  a2 = fminf(a2, red[16 + i]);
            a3 = fmaxf(a3, red[24 + i]); a4 = fmaxf(a4, red[32 + i]); a5 = fmaxf(a5, red[40 + i]);
        }
        float hx = (a3 - a0) * (1.0f / G) * 1.000001f + 1e-30f;
        float hy = (a4 - a1) * (1.0f / G) * 1.000001f + 1e-30f;
        float hz = (a5 - a2) * (1.0f / G) * 1.000001f + 1e-30f;
        sbox[0] = a0; sbox[1] = a1; sbox[2] = a2;
        sbox[3] = hx; sbox[4] = hy; sbox[5] = hz;
        sbox[6] = 1.0f / hx; sbox[7] = 1.0f / hy; sbox[8] = 1.0f / hz;
        for (int i = 0; i < 9; i++) g_box[b][i] = sbox[i];
    }
    __syncthreads();

    for (int c = tid; c < NCELL; c += blockDim.x) cnt[c] = 0;
    __syncthreads();
    for (int i = tid; i < NSP; i += blockDim.x) {
        int c = cell_of(sp[3*i], sp[3*i+1], sp[3*i+2], sbox);
        atomicAdd(&cnt[c], 1);
    }
    __syncthreads();

    int c0 = tid * CHUNK, s = 0;
    for (int j = 0; j < CHUNK; j++) { int c = c0 + j; if (c < NCELL) s += cnt[c]; }
    tot[tid] = s;
    __syncthreads();
    if (tid == 0) { int run = 0; for (int i = 0; i < 256; i++) { int v = tot[i]; tot[i] = run; run += v; } }
    __syncthreads();
    int run = tot[tid];
    for (int j = 0; j < CHUNK; j++) { int c = c0 + j; if (c < NCELL) { st[c] = run; run += cnt[c]; } }
    __syncthreads();
    if (tid == 0) st[NCELL] = NSP;
    __syncthreads();

    for (int c = tid; c <= NCELL; c += blockDim.x) g_cst[b][c] = (unsigned short)st[c];
    for (int c = tid; c < NCELL; c += blockDim.x) cnt[c] = st[c];   // cnt becomes cursor
    __syncthreads();

    for (int i = tid; i < NSP; i += blockDim.x) {
        float x = sp[3*i], y = sp[3*i+1], z = sp[3*i+2];
        int c = cell_of(x, y, z, sbox);
        int pos = atomicAdd(&cnt[c], 1);
        g_spk[b][pos] = make_float4(x, y, z, __int_as_float(i << 12));
    }
}

// ---------------- kernel 2: count queries per cell ----------------
__global__ void k_count_pts(const float* __restrict__ points) {
    const int b = blockIdx.y;
    const int p = blockIdx.x * blockDim.x + threadIdx.x;
    if (p >= NPTS) return;
    const float* pp = points + ((size_t)b * NPTS + p) * 3;
    float bx[9];
#pragma unroll
    for (int i = 0; i < 9; i++) bx[i] = g_box[b][i];
    atomicAdd(&g_pcnt[b][cell_of(pp[0], pp[1], pp[2], bx)], 1);
}

// ---------------- kernel 3: scan query counts -> cursors ----------------
__global__ void k_init_cursors() {
    const int b = blockIdx.x, tid = threadIdx.x;
    __shared__ int tot[256];
    int c0 = tid * CHUNK, s = 0;
    for (int j = 0; j < CHUNK; j++) { int c = c0 + j; if (c < NCELL) s += g_pcnt[b][c]; }
    tot[tid] = s;
    __syncthreads();
    if (tid == 0) { int run = 0; for (int i = 0; i < 256; i++) { int v = tot[i]; tot[i] = run; run += v; } }
    __syncthreads();
    int run = tot[tid];
    for (int j = 0; j < CHUNK; j++) { int c = c0 + j; if (c < NCELL) { g_pcur[b][c] = run; run += g_pcnt[b][c]; } }
}

// ---------------- kernel 4: scatter queries into cell-sorted order ----------------
__global__ void k_scatter_pts(const float* __restrict__ points) {
    const int b = blockIdx.y;
    const int p = blockIdx.x * blockDim.x + threadIdx.x;
    if (p >= NPTS) return;
    const float* pp = points + ((size_t)b * NPTS + p) * 3;
    float x = pp[0], y = pp[1], z = pp[2];
    float bx[9];
#pragma unroll
    for (int i = 0; i < 9; i++) bx[i] = g_box[b][i];
    int pos = atomicAdd(&g_pcur[b][cell_of(x, y, z, bx)], 1);
    g_pts[b][pos] = make_float4(x, y, z, __int_as_float(p));
}

// ---------------- kernel 5: main — uniform 3^3 strip scan + rare shell fallback ----------------
static constexpr int SM_MAIN = NSP * 16 + 16 * 4 + (NCELL + 1) * 2;  // 80066

__global__ __launch_bounds__(TMAIN, 2) void k_main(float* __restrict__ out) {
    extern __shared__ float smf[];
    float4* spk = (float4*)smf;                        // NSP float4
    float*  sbb = (float*)(spk + NSP);                 // 9 floats (+pad)
    unsigned short* cst = (unsigned short*)(sbb + 16); // NCELL+1

    const int b = blockIdx.y, tid = threadIdx.x;
    for (int i = tid; i < NSP; i += TMAIN) spk[i] = g_spk[b][i];
    for (int i = tid; i <= NCELL; i += TMAIN) cst[i] = g_cst[b][i];
    if (tid < 9) sbb[tid] = g_box[b][tid];
    __syncthreads();

    const unsigned FULL = 0xffffffffu;
    int t = blockIdx.x * TMAIN + tid;
    const bool valid = (t < NPTS);
    if (!valid) t = NPTS - 1;            // duplicate last point; keeps warp full

    const float4 P = g_pts[b][t];
    const float px = P.x, py = P.y, pz = P.z;
    const int orig = __float_as_int(P.w);

    const float mnx = sbb[0], mny = sbb[1], mnz = sbb[2];
    const float hx = sbb[3], hy = sbb[4], hz = sbb[5];
    const int cx = min(G - 1, max(0, (int)((px - mnx) * sbb[6])));
    const int cy = min(G - 1, max(0, (int)((py - mny) * sbb[7])));
    const int cz = min(G - 1, max(0, (int)((pz - mnz) * sbb[8])));

    float bd[KNN];
    int   bo[KNN];   // key = (orig_site_idx << 12) | sorted_pos — lex order == jax tie-break
    auto insert = [&](float d, int kk) {
#pragma unroll
        for (int k = 0; k < KNN; k++) {
            const bool sw = (d < bd[k]) || ((d == bd[k]) && (kk < bo[k]));
            if (sw) {
                const float td = bd[k]; bd[k] = d;  d = td;
                const int   ti = bo[k]; bo[k] = kk; kk = ti;
            }
        }
    };
    auto scan_range = [&](int m, int m1) {
        for (; m + 2 <= m1; m += 2) {
            const float4 S0 = spk[m];
            const float4 S1 = spk[m + 1];
            const float dx0 = px - S0.x, dy0 = py - S0.y, dz0 = pz - S0.z;
            const float dx1 = px - S1.x, dy1 = py - S1.y, dz1 = pz - S1.z;
            const float d20 = fmaf(dz0, dz0, fmaf(dy0, dy0, dx0 * dx0));
            const float d21 = fmaf(dz1, dz1, fmaf(dy1, dy1, dx1 * dx1));
            if (d20 <= bd[KNN - 1]) insert(d20, __float_as_int(S0.w) | m);
            if (d21 <= bd[KNN - 1]) insert(d21, __float_as_int(S1.w) | (m + 1));
        }
        if (m < m1) {
            const float4 S = spk[m];
            const float dx = px - S.x, dy = py - S.y, dz = pz - S.z;
            const float d2 = fmaf(dz, dz, fmaf(dy, dy, dx * dx));
            if (d2 <= bd[KNN - 1]) insert(d2, __float_as_int(S.w) | m);
        }
    };

    // ---- Phase 1: fixed 3x3x3 box (clamped), as 9 contiguous z-strips ----
    const int xl = max(cx - 1, 0), xh = min(cx + 1, G - 1);
    const int yl = max(cy - 1, 0), yh = min(cy + 1, G - 1);
    const int zl = max(cz - 1, 0), zh = min(cz + 1, G - 1);

    // count first (prefix differences only), to enable tight sentinel prefill
    int count = 0;
    for (int X = xl; X <= xh; X++) {
        for (int Y = yl; Y <= yh; Y++) {
            const int base = (X * G + Y) * G;
            count += (int)cst[base + zh + 1] - (int)cst[base + zl];
        }
    }
    float T = 3.4e38f;
    if (count >= KNN) {
        const float fx = fmaxf(px - (mnx + (float)xl * hx), (mnx + (float)(xh + 1) * hx) - px);
        const float fy = fmaxf(py - (mny + (float)yl * hy), (mny + (float)(yh + 1) * hy) - py);
        const float fz = fmaxf(pz - (mnz + (float)zl * hz), (mnz + (float)(zh + 1) * hz) - pz);
        T = fmaf(fx, fx, fmaf(fy, fy, fz * fz)) * 1.0005f;   // fp-safe: all box sites have d2 <= T
    }
#pragma unroll
    for (int k = 0; k < KNN; k++) { bd[k] = T; bo[k] = SENT; }

    for (int X = xl; X <= xh; X++) {
        for (int Y = yl; Y <= yh; Y++) {
            const int base = (X * G + Y) * G;
            scan_range(cst[base + zl], cst[base + zh + 1]);
        }
    }

    // stop test vs box faces (clamped faces need no bound: all sites inside bbox)
    // bd[10] is a real site iff count>=11 (then all 11 sentinel slots were displaced)
    bool done;
    {
        float bnd = 3.0e38f;
        if (xl > 0)     bnd = fminf(bnd, px - (mnx + (float)xl * hx));
        if (xh < G - 1) bnd = fminf(bnd, (mnx + (float)(xh + 1) * hx) - px);
        if (yl > 0)     bnd = fminf(bnd, py - (mny + (float)yl * hy));
        if (yh < G - 1) bnd = fminf(bnd, (mny + (float)(yh + 1) * hy) - py);
        if (zl > 0)     bnd = fminf(bnd, pz - (mnz + (float)zl * hz));
        if (zh < G - 1) bnd = fminf(bnd, (mnz + (float)(zh + 1) * hz) - pz);
        done = (count >= KNN) && (bd[KNN - 1] < 3.0e38f) && (bnd > 0.0f) &&
               (bnd * bnd >= bd[KNN - 1] * 1.0002f);
    }

    // ---- Phase 2 (rare): surface shells from r=2 with per-cell rect skip ----
    if (!__all_sync(FULL, done)) {
        auto rect2_of = [&](int X, int Y, int Z) -> float {
            const float lx = mnx + (float)X * hx;
            const float ly = mny + (float)Y * hy;
            const float lz = mnz + (float)Z * hz;
            const float ax = fmaxf(0.0f, fmaxf(lx - px, px - (lx + hx)));
            const float ay = fmaxf(0.0f, fmaxf(ly - py, py - (ly + hy)));
            const float az = fmaxf(0.0f, fmaxf(lz - pz, pz - (lz + hz)));
            return fmaf(az, az, fmaf(ay, ay, ax * ax));
        };
        auto scan_cell = [&](int c) { scan_range(cst[c], cst[c + 1]); };

        for (int r = 2; r < G; r++) {
            if (!done) {
                const int szl = max(cz - r, 0), szh = min(cz + r, G - 1);
                const int syl = max(cy - r, 0), syh = min(cy + r, G - 1);
                const int sxl = max(cx - r, 0), sxh = min(cx + r, G - 1);
                for (int Z = szl; Z <= szh; Z++) {
                    const bool zb = (Z == cz - r) || (Z == cz + r);
                    for (int Y = syl; Y <= syh; Y++) {
                        if (zb || (Y == cy - r) || (Y == cy + r)) {
                            for (int X = sxl; X <= sxh; X++)
                                if (rect2_of(X, Y, Z) <= bd[KNN - 1]) scan_cell((X * G + Y) * G + Z);
                        } else {
                            int X = cx - r;
                            if (X >= 0 && rect2_of(X, Y, Z) <= bd[KNN - 1]) scan_cell((X * G + Y) * G + Z);
                            X = cx + r;
                            if (X <= G - 1 && rect2_of(X, Y, Z) <= bd[KNN - 1]) scan_cell((X * G + Y) * G + Z);
                        }
                    }
                }
                const bool full = (sxl == 0 && sxh == G - 1 && syl == 0 && syh == G - 1 &&
                                   szl == 0 && szh == G - 1);
                float bnd = 3.0e38f;
                if (sxl > 0)     bnd = fminf(bnd, px - (mnx + (float)sxl * hx));
                if (sxh < G - 1) bnd = fminf(bnd, (mnx + (float)(sxh + 1) * hx) - px);
                if (syl > 0)     bnd = fminf(bnd, py - (mny + (float)syl * hy));
                if (syh < G - 1) bnd = fminf(bnd, (mny + (float)(syh + 1) * hy) - py);
                if (szl > 0)     bnd = fminf(bnd, pz - (mnz + (float)szl * hz));
                if (szh < G - 1) bnd = fminf(bnd, (mnz + (float)(szh + 1) * hz) - pz);
                done = full || (bd[KNN - 1] < 3.0e38f && bnd > 0.0f &&
                                bnd * bnd >= bd[KNN - 1] * 1.0002f);
            }
            if (__all_sync(FULL, done)) break;
        }
    }

    // ---- Voronoi-edge epilogue on the 11 selected sites ----
    const int p0 = min(bo[0] & 4095, NSP - 1);
    const float4 C = spk[p0];
    const float tx = px - C.x, ty = py - C.y, tz = pz - C.z;
    float best = 3.4e38f;
#pragma unroll
    for (int j = 1; j < KNN; j++) {
        const int pj = min(bo[j] & 4095, NSP - 1);
        const float4 E = spk[pj];
        const float ex = E.x - C.x, ey = E.y - C.y, ez = E.z - C.z;
        const float el2 = fmaf(ez, ez, fmaf(ey, ey, ex * ex));
        const float dp  = fmaf(tz, ez, fmaf(ty, ey, tx * ex));
        const float tt  = fmaf(-0.5f, el2, dp) * rsqrtf(el2);  // (dp - el2/2)/sqrt(el2)
        best = fminf(best, tt * tt);
    }
    if (valid) out[(size_t)b * NPTS + orig] = best;
}

// ---------------- launch ----------------
extern "C" void kernel_launch(void* const* d_in, const int* in_sizes, int n_in,
                              void* d_out, int out_size)
{
    const float* points  = (const float*)d_in[0];
    const float* spoints = (const float*)d_in[1];
    float* out = (float*)d_out;

    cudaFuncSetAttribute(k_setup_sites, cudaFuncAttributeMaxDynamicSharedMemorySize, SM_SETUP);
    cudaFuncSetAttribute(k_main,        cudaFuncAttributeMaxDynamicSharedMemorySize, SM_MAIN);

    k_setup_sites<<<NB, 256, SM_SETUP>>>(spoints);
    dim3 gp((NPTS + 255) / 256, NB);
    k_count_pts<<<gp, 256>>>(points);
    k_init_cursors<<<NB, 256>>>();
    k_scatter_pts<<<gp, 256>>>(points);
    k_main<<<dim3(BLKS_MAIN, NB), TMAIN, SM_MAIN>>>(out);
}

// round 14
// speedup vs baseline: 2.0980x; 2.0980x over previous
#include <cuda_runtime.h>

#define KNN      11
#define NPTS     50000
#define NSP      4000
#define NB       2
#define G        20
#define NCELL    (G*G*G)                  // 8000
#define CHUNK    ((NCELL + 255) / 256)    // 32
#define TMAIN    512
#define BLKS_MAIN ((NPTS + TMAIN - 1) / TMAIN)
#define SENT     0x7FFFFFFF

// ---------------- device scratch (no allocations allowed) ----------------
__device__ float4         g_spk[NB][NSP];       // cell-sorted sites, w = int_as_float(sidx<<12)
__device__ unsigned short g_cst[NB][NCELL + 1]; // site cell start offsets
__device__ float          g_box[NB][9];         // mn[3], h[3], inv_h[3]
__device__ int            g_pcnt[NB][NCELL];
__device__ int            g_pcur[NB][NCELL];
__device__ float4         g_pts[NB][NPTS];      // cell-sorted queries (w = orig idx)

__device__ __forceinline__ int cell_of(float x, float y, float z, const float* bx) {
    int cx = (int)((x - bx[0]) * bx[6]); cx = min(G - 1, max(0, cx));
    int cy = (int)((y - bx[1]) * bx[7]); cy = min(G - 1, max(0, cy));
    int cz = (int)((z - bx[2]) * bx[8]); cz = min(G - 1, max(0, cz));
    return (cx * G + cy) * G + cz;
}

// ---------------- kernel 1: bin sites into grid (one block per batch) ----------------
static constexpr int SM_SETUP = (NCELL + NCELL + 1 + 256) * 4 + 48 * 4;

__global__ void k_setup_sites(const float* __restrict__ spoints) {
    extern __shared__ int sm[];
    int*   cnt = sm;                  // NCELL
    int*   st  = cnt + NCELL;         // NCELL+1
    int*   tot = st + NCELL + 1;      // 256
    float* red = (float*)(tot + 256); // 48
    __shared__ float sbox[9];

    const int b = blockIdx.x, tid = threadIdx.x;
    const float* sp = spoints + (size_t)b * NSP * 3;

    for (int c = tid; c < NCELL; c += blockDim.x) g_pcnt[b][c] = 0;

    float mnx = 3e38f, mny = 3e38f, mnz = 3e38f;
    float mxx = -3e38f, mxy = -3e38f, mxz = -3e38f;
    for (int i = tid; i < NSP; i += blockDim.x) {
        float x = sp[3*i], y = sp[3*i+1], z = sp[3*i+2];
        mnx = fminf(mnx, x); mxx = fmaxf(mxx, x);
        mny = fminf(mny, y); mxy = fmaxf(mxy, y);
        mnz = fminf(mnz, z); mxz = fmaxf(mxz, z);
    }
#pragma unroll
    for (int o = 16; o; o >>= 1) {
        mnx = fminf(mnx, __shfl_xor_sync(0xffffffffu, mnx, o));
        mny = fminf(mny, __shfl_xor_sync(0xffffffffu, mny, o));
        mnz = fminf(mnz, __shfl_xor_sync(0xffffffffu, mnz, o));
        mxx = fmaxf(mxx, __shfl_xor_sync(0xffffffffu, mxx, o));
        mxy = fmaxf(mxy, __shfl_xor_sync(0xffffffffu, mxy, o));
        mxz = fmaxf(mxz, __shfl_xor_sync(0xffffffffu, mxz, o));
    }
    int w = tid >> 5;
    if ((tid & 31) == 0) {
        red[w] = mnx; red[8 + w] = mny; red[16 + w] = mnz;
        red[24 + w] = mxx; red[32 + w] = mxy; red[40 + w] = mxz;
    }
    __syncthreads();
    if (tid == 0) {
        float a0 = red[0], a1 = red[8], a2 = red[16], a3 = red[24], a4 = red[32], a5 = red[40];
        for (int i = 1; i < 8; i++) {
            a0 = fminf(a0, red[i]);      a1 = fminf(a1, red[8 + i]);  a2 = fminf(a2, red[16 + i]);
            a3 = fmaxf(a3, red[24 + i]); a4 = fmaxf(a4, red[32 + i]); a5 = fmaxf(a5, red[40 + i]);
        }
        float hx = (a3 - a0) * (1.0f / G) * 1.000001f + 1e-30f;
        float hy = (a4 - a1) * (1.0f / G) * 1.000001f + 1e-30f;
        float hz = (a5 - a2) * (1.0f / G) * 1.000001f + 1e-30f;
        sbox[0] = a0; sbox[1] = a1; sbox[2] = a2;
        sbox[3] = hx; sbox[4] = hy; sbox[5] = hz;
        sbox[6] = 1.0f / hx; sbox[7] = 1.0f / hy; sbox[8] = 1.0f / hz;
        for (int i = 0; i < 9; i++) g_box[b][i] = sbox[i];
    }
    __syncthreads();

    for (int c = tid; c < NCELL; c += blockDim.x) cnt[c] = 0;
    __syncthreads();
    for (int i = tid; i < NSP; i += blockDim.x) {
        int c = cell_of(sp[3*i], sp[3*i+1], sp[3*i+2], sbox);
        atomicAdd(&cnt[c], 1);
    }
    __syncthreads();

    int c0 = tid * CHUNK, s = 0;
    for (int j = 0; j < CHUNK; j++) { int c = c0 + j; if (c < NCELL) s += cnt[c]; }
    tot[tid] = s;
    __syncthreads();
    if (tid == 0) { int run = 0; for (int i = 0; i < 256; i++) { int v = tot[i]; tot[i] = run; run += v; } }
    __syncthreads();
    int run = tot[tid];
    for (int j = 0; j < CHUNK; j++) { int c = c0 + j; if (c < NCELL) { st[c] = run; run += cnt[c]; } }
    __syncthreads();
    if (tid == 0) st[NCELL] = NSP;
    __syncthreads();

    for (int c = tid; c <= NCELL; c += blockDim.x) g_cst[b][c] = (unsigned short)st[c];
    for (int c = tid; c < NCELL; c += blockDim.x) cnt[c] = st[c];   // cnt becomes cursor
    __syncthreads();

    for (int i = tid; i < NSP; i += blockDim.x) {
        float x = sp[3*i], y = sp[3*i+1], z = sp[3*i+2];
        int c = cell_of(x, y, z, sbox);
        int pos = atomicAdd(&cnt[c], 1);
        g_spk[b][pos] = make_float4(x, y, z, __int_as_float(i << 12));
    }
}

// ---------------- kernel 2: count queries per cell ----------------
__global__ void k_count_pts(const float* __restrict__ points) {
    const int b = blockIdx.y;
    const int p = blockIdx.x * blockDim.x + threadIdx.x;
    if (p >= NPTS) return;
    const float* pp = points + ((size_t)b * NPTS + p) * 3;
    float bx[9];
#pragma unroll
    for (int i = 0; i < 9; i++) bx[i] = g_box[b][i];
    atomicAdd(&g_pcnt[b][cell_of(pp[0], pp[1], pp[2], bx)], 1);
}

// ---------------- kernel 3: scan query counts -> cursors ----------------
__global__ void k_init_cursors() {
    const int b = blockIdx.x, tid = threadIdx.x;
    __shared__ int tot[256];
    int c0 = tid * CHUNK, s = 0;
    for (int j = 0; j < CHUNK; j++) { int c = c0 + j; if (c < NCELL) s += g_pcnt[b][c]; }
    tot[tid] = s;
    __syncthreads();
    if (tid == 0) { int run = 0; for (int i = 0; i < 256; i++) { int v = tot[i]; tot[i] = run; run += v; } }
    __syncthreads();
    int run = tot[tid];
    for (int j = 0; j < CHUNK; j++) { int c = c0 + j; if (c < NCELL) { g_pcur[b][c] = run; run += g_pcnt[b][c]; } }
}

// ---------------- kernel 4: scatter queries into cell-sorted order ----------------
__global__ void k_scatter_pts(const float* __restrict__ points) {
    const int b = blockIdx.y;
    const int p = blockIdx.x * blockDim.x + threadIdx.x;
    if (p >= NPTS) return;
    const float* pp = points + ((size_t)b * NPTS + p) * 3;
    float x = pp[0], y = pp[1], z = pp[2];
    float bx[9];
#pragma unroll
    for (int i = 0; i < 9; i++) bx[i] = g_box[b][i];
    int pos = atomicAdd(&g_pcur[b][cell_of(x, y, z, bx)], 1);
    g_pts[b][pos] = make_float4(x, y, z, __int_as_float(p));
}

// ---------------- kernel 5: main — single-shot: count box -> box scan -> exact ball sweep ----------------
static constexpr int SM_MAIN = NSP * 16 + 16 * 4 + (NCELL + 1) * 2;  // 80066

__global__ __launch_bounds__(TMAIN, 2) void k_main(float* __restrict__ out) {
    extern __shared__ float smf[];
    float4* spk = (float4*)smf;                        // NSP float4
    float*  sbb = (float*)(spk + NSP);                 // 9 floats (+pad)
    unsigned short* cst = (unsigned short*)(sbb + 16); // NCELL+1

    const int b = blockIdx.y, tid = threadIdx.x;
    for (int i = tid; i < NSP; i += TMAIN) spk[i] = g_spk[b][i];
    for (int i = tid; i <= NCELL; i += TMAIN) cst[i] = g_cst[b][i];
    if (tid < 9) sbb[tid] = g_box[b][tid];
    __syncthreads();

    int t = blockIdx.x * TMAIN + tid;
    const bool valid = (t < NPTS);
    if (!valid) t = NPTS - 1;            // duplicate last point; harmless

    const float4 P = g_pts[b][t];
    const float px = P.x, py = P.y, pz = P.z;
    const int orig = __float_as_int(P.w);

    const float mnx = sbb[0], mny = sbb[1], mnz = sbb[2];
    const float hx = sbb[3], hy = sbb[4], hz = sbb[5];
    const float ihx = sbb[6], ihy = sbb[7], ihz = sbb[8];
    const int cx = min(G - 1, max(0, (int)((px - mnx) * ihx)));
    const int cy = min(G - 1, max(0, (int)((py - mny) * ihy)));
    const int cz = min(G - 1, max(0, (int)((pz - mnz) * ihz)));

    float bd[KNN];
    int   bo[KNN];   // key = (orig_site_idx << 12) | sorted_pos — lex order == jax tie-break
    auto insert = [&](float d, int kk) {
#pragma unroll
        for (int k = 0; k < KNN; k++) {
            const bool sw = (d < bd[k]) || ((d == bd[k]) && (kk < bo[k]));
            if (sw) {
                const float td = bd[k]; bd[k] = d;  d = td;
                const int   ti = bo[k]; bo[k] = kk; kk = ti;
            }
        }
    };
    auto scan_range = [&](int m, int m1) {
        for (; m + 2 <= m1; m += 2) {
            const float4 S0 = spk[m];
            const float4 S1 = spk[m + 1];
            const float dx0 = px - S0.x, dy0 = py - S0.y, dz0 = pz - S0.z;
            const float dx1 = px - S1.x, dy1 = py - S1.y, dz1 = pz - S1.z;
            const float d20 = fmaf(dz0, dz0, fmaf(dy0, dy0, dx0 * dx0));
            const float d21 = fmaf(dz1, dz1, fmaf(dy1, dy1, dx1 * dx1));
            if (d20 <= bd[KNN - 1]) insert(d20, __float_as_int(S0.w) | m);
            if (d21 <= bd[KNN - 1]) insert(d21, __float_as_int(S1.w) | (m + 1));
        }
        if (m < m1) {
            const float4 S = spk[m];
            const float dx = px - S.x, dy = py - S.y, dz = pz - S.z;
            const float d2 = fmaf(dz, dz, fmaf(dy, dy, dx * dx));
            if (d2 <= bd[KNN - 1]) insert(d2, __float_as_int(S.w) | m);
        }
    };

    // ---- Phase A: expand box around home cell until it holds >= 11 sites (counts only) ----
    int bxl, bxh, byl, byh, bzl, bzh;
    for (int r = 1; ; r++) {
        bxl = max(cx - r, 0); bxh = min(cx + r, G - 1);
        byl = max(cy - r, 0); byh = min(cy + r, G - 1);
        bzl = max(cz - r, 0); bzh = min(cz + r, G - 1);
        int count = 0;
        for (int X = bxl; X <= bxh; X++) {
            const int rb = X * G;
            for (int Y = byl; Y <= byh; Y++) {
                const int base = (rb + Y) * G;
                count += (int)cst[base + bzh + 1] - (int)cst[base + bzl];
            }
        }
        if (count >= KNN) break;
        if (bxl == 0 && bxh == G - 1 && byl == 0 && byh == G - 1 &&
            bzl == 0 && bzh == G - 1) break;       // whole grid: count = NSP >= 11
    }

    // corner-distance upper bound on any box site's d2 (with fp slack) -> insert gate
    {
        const float fx = fmaxf(px - (mnx + (float)bxl * hx), (mnx + (float)(bxh + 1) * hx) - px);
        const float fy = fmaxf(py - (mny + (float)byl * hy), (mny + (float)(byh + 1) * hy) - py);
        const float fz = fmaxf(pz - (mnz + (float)bzl * hz), (mnz + (float)(bzh + 1) * hz) - pz);
        const float T = fmaf(fx, fx, fmaf(fy, fy, fz * fz)) * 1.0005f;
#pragma unroll
        for (int k = 0; k < KNN; k++) { bd[k] = T; bo[k] = SENT; }
    }

    // ---- Phase B: scan the box (contiguous z-strips). bd[10] becomes a REAL upper bound ----
    for (int X = bxl; X <= bxh; X++) {
        const int rb = X * G;
        for (int Y = byl; Y <= byh; Y++) {
            const int base = (rb + Y) * G;
            scan_range(cst[base + bzl], cst[base + bzh + 1]);
        }
    }

    // ---- Phase C: exact ball sweep: all cells intersecting ball(p, sqrt(bd10)), minus box ----
    {
        const float T2 = bd[KNN - 1] * 1.0005f;      // count>=11 => bd[10] is real
        const float sR = sqrtf(T2);
        const int qxl = min(G - 1, max(0, (int)((px - sR - mnx) * ihx)));
        const int qxh = min(G - 1, max(0, (int)((px + sR - mnx) * ihx)));
        const int qyl = min(G - 1, max(0, (int)((py - sR - mny) * ihy)));
        const int qyh = min(G - 1, max(0, (int)((py + sR - mny) * ihy)));

        for (int X = qxl; X <= qxh; X++) {
            const float lx = mnx + (float)X * hx;
            const float ax = fmaxf(0.0f, fmaxf(lx - px, px - (lx + hx)));
            const float ax2 = ax * ax;
            if (ax2 > T2) continue;
            const bool inBx = (X >= bxl) && (X <= bxh);
            const int rb = X * G;
            for (int Y = qyl; Y <= qyh; Y++) {
                // dynamic gate: current bd[10] only shrinks; still an upper bound on true d2_11
                const float cur = bd[KNN - 1] * 1.0005f;
                const float ly = mny + (float)Y * hy;
                const float ay = fmaxf(0.0f, fmaxf(ly - py, py - (ly + hy)));
                const float dxy2 = fmaf(ay, ay, ax2);
                if (dxy2 > cur) continue;
                const float sq = sqrtf(fmaxf(cur - dxy2, 0.0f));
                int zlo = min(G - 1, max(0, (int)((pz - sq - mnz) * ihz)));
                int zhi = min(G - 1, max(0, (int)((pz + sq - mnz) * ihz)));
                const int base = (rb + Y) * G;
                if (inBx && Y >= byl && Y <= byh) {
                    // subtract already-scanned z interval [bzl, bzh]
                    const int z1h = min(zhi, bzl - 1);
                    if (zlo <= z1h) scan_range(cst[base + zlo], cst[base + z1h + 1]);
                    const int z2l = max(zlo, bzh + 1);
                    if (z2l <= zhi) scan_range(cst[base + z2l], cst[base + zhi + 1]);
                } else {
                    scan_range(cst[base + zlo], cst[base + zhi + 1]);
                }
            }
        }
    }

    // ---- Voronoi-edge epilogue on the 11 selected sites ----
    const int p0 = min(bo[0] & 4095, NSP - 1);
    const float4 C = spk[p0];
    const float tx = px - C.x, ty = py - C.y, tz = pz - C.z;
    float best = 3.4e38f;
#pragma unroll
    for (int j = 1; j < KNN; j++) {
        const int pj = min(bo[j] & 4095, NSP - 1);
        const float4 E = spk[pj];
        const float ex = E.x - C.x, ey = E.y - C.y, ez = E.z - C.z;
        const float el2 = fmaf(ez, ez, fmaf(ey, ey, ex * ex));
        const float dp  = fmaf(tz, ez, fmaf(ty, ey, tx * ex));
        const float tt  = fmaf(-0.5f, el2, dp) * rsqrtf(el2);  // (dp - el2/2)/sqrt(el2)
        best = fminf(best, tt * tt);
    }
    if (valid) out[(size_t)b * NPTS + orig] = best;
}

// ---------------- launch ----------------
extern "C" void kernel_launch(void* const* d_in, const int* in_sizes, int n_in,
                              void* d_out, int out_size)
{
    const float* points  = (const float*)d_in[0];
    const float* spoints = (const float*)d_in[1];
    float* out = (float*)d_out;

    cudaFuncSetAttribute(k_setup_sites, cudaFuncAttributeMaxDynamicSharedMemorySize, SM_SETUP);
    cudaFuncSetAttribute(k_main,        cudaFuncAttributeMaxDynamicSharedMemorySize, SM_MAIN);

    k_setup_sites<<<NB, 256, SM_SETUP>>>(spoints);
    dim3 gp((NPTS + 255) / 256, NB);
    k_count_pts<<<gp, 256>>>(points);
    k_init_cursors<<<NB, 256>>>();
    k_scatter_pts<<<gp, 256>>>(points);
    k_main<<<dim3(BLKS_MAIN, NB), TMAIN, SM_MAIN>>>(out);
}

// round 15
// speedup vs baseline: 2.2736x; 1.0837x over previous
#include <cuda_runtime.h>

#define KNN      11
#define NPTS     50000
#define NSP      4000
#define NB       2
#define G        20
#define NCELL    (G*G*G)                  // 8000
#define CHUNK    ((NCELL + 255) / 256)    // 32
#define TMAIN    384
#define BLKS_MAIN ((NPTS + TMAIN - 1) / TMAIN)
#define SENT     0x7FFFFFFF

// ---------------- device scratch (no allocations allowed) ----------------
__device__ float4         g_spk[NB][NSP];       // cell-sorted sites, w = int_as_float(sidx<<12)
__device__ unsigned short g_cst[NB][NCELL + 1]; // site cell start offsets
__device__ float          g_box[NB][9];         // mn[3], h[3], inv_h[3]
__device__ int            g_pcnt[NB][NCELL];
__device__ int            g_pcur[NB][NCELL];
__device__ float4         g_pts[NB][NPTS];      // cell-sorted queries (w = orig idx)

__device__ __forceinline__ int cell_of(float x, float y, float z, const float* bx) {
    int cx = (int)((x - bx[0]) * bx[6]); cx = min(G - 1, max(0, cx));
    int cy = (int)((y - bx[1]) * bx[7]); cy = min(G - 1, max(0, cy));
    int cz = (int)((z - bx[2]) * bx[8]); cz = min(G - 1, max(0, cz));
    return (cx * G + cy) * G + cz;
}

// ---------------- kernel 1: bin sites into grid (one block per batch) ----------------
static constexpr int SM_SETUP = (NCELL + NCELL + 1 + 256) * 4 + 48 * 4;

__global__ void k_setup_sites(const float* __restrict__ spoints) {
    extern __shared__ int sm[];
    int*   cnt = sm;                  // NCELL
    int*   st  = cnt + NCELL;         // NCELL+1
    int*   tot = st + NCELL + 1;      // 256
    float* red = (float*)(tot + 256); // 48
    __shared__ float sbox[9];

    const int b = blockIdx.x, tid = threadIdx.x;
    const float* sp = spoints + (size_t)b * NSP * 3;

    for (int c = tid; c < NCELL; c += blockDim.x) g_pcnt[b][c] = 0;

    float mnx = 3e38f, mny = 3e38f, mnz = 3e38f;
    float mxx = -3e38f, mxy = -3e38f, mxz = -3e38f;
    for (int i = tid; i < NSP; i += blockDim.x) {
        float x = sp[3*i], y = sp[3*i+1], z = sp[3*i+2];
        mnx = fminf(mnx, x); mxx = fmaxf(mxx, x);
        mny = fminf(mny, y); mxy = fmaxf(mxy, y);
        mnz = fminf(mnz, z); mxz = fmaxf(mxz, z);
    }
#pragma unroll
    for (int o = 16; o; o >>= 1) {
        mnx = fminf(mnx, __shfl_xor_sync(0xffffffffu, mnx, o));
        mny = fminf(mny, __shfl_xor_sync(0xffffffffu, mny, o));
        mnz = fminf(mnz, __shfl_xor_sync(0xffffffffu, mnz, o));
        mxx = fmaxf(mxx, __shfl_xor_sync(0xffffffffu, mxx, o));
        mxy = fmaxf(mxy, __shfl_xor_sync(0xffffffffu, mxy, o));
        mxz = fmaxf(mxz, __shfl_xor_sync(0xffffffffu, mxz, o));
    }
    int w = tid >> 5;
    if ((tid & 31) == 0) {
        red[w] = mnx; red[8 + w] = mny; red[16 + w] = mnz;
        red[24 + w] = mxx; red[32 + w] = mxy; red[40 + w] = mxz;
    }
    __syncthreads();
    if (tid == 0) {
        float a0 = red[0], a1 = red[8], a2 = red[16], a3 = red[24], a4 = red[32], a5 = red[40];
        for (int i = 1; i < 8; i++) {
            a0 = fminf(a0, red[i]);      a1 = fminf(a1, red[8 + i]);  a2 = fminf(a2, red[16 + i]);
            a3 = fmaxf(a3, red[24 + i]); a4 = fmaxf(a4, red[32 + i]); a5 = fmaxf(a5, red[40 + i]);
        }
        float hx = (a3 - a0) * (1.0f / G) * 1.000001f + 1e-30f;
        float hy = (a4 - a1) * (1.0f / G) * 1.000001f + 1e-30f;
        float hz = (a5 - a2) * (1.0f / G) * 1.000001f + 1e-30f;
        sbox[0] = a0; sbox[1] = a1; sbox[2] = a2;
        sbox[3] = hx; sbox[4] = hy; sbox[5] = hz;
        sbox[6] = 1.0f / hx; sbox[7] = 1.0f / hy; sbox[8] = 1.0f / hz;
        for (int i = 0; i < 9; i++) g_box[b][i] = sbox[i];
    }
    __syncthreads();

    for (int c = tid; c < NCELL; c += blockDim.x) cnt[c] = 0;
    __syncthreads();
    for (int i = tid; i < NSP; i += blockDim.x) {
        int c = cell_of(sp[3*i], sp[3*i+1], sp[3*i+2], sbox);
        atomicAdd(&cnt[c], 1);
    }
    __syncthreads();

    int c0 = tid * CHUNK, s = 0;
    for (int j = 0; j < CHUNK; j++) { int c = c0 + j; if (c < NCELL) s += cnt[c]; }
    tot[tid] = s;
    __syncthreads();
    if (tid == 0) { int run = 0; for (int i = 0; i < 256; i++) { int v = tot[i]; tot[i] = run; run += v; } }
    __syncthreads();
    int run = tot[tid];
    for (int j = 0; j < CHUNK; j++) { int c = c0 + j; if (c < NCELL) { st[c] = run; run += cnt[c]; } }
    __syncthreads();
    if (tid == 0) st[NCELL] = NSP;
    __syncthreads();

    for (int c = tid; c <= NCELL; c += blockDim.x) g_cst[b][c] = (unsigned short)st[c];
    for (int c = tid; c < NCELL; c += blockDim.x) cnt[c] = st[c];   // cnt becomes cursor
    __syncthreads();

    for (int i = tid; i < NSP; i += blockDim.x) {
        float x = sp[3*i], y = sp[3*i+1], z = sp[3*i+2];
        int c = cell_of(x, y, z, sbox);
        int pos = atomicAdd(&cnt[c], 1);
        g_spk[b][pos] = make_float4(x, y, z, __int_as_float(i << 12));
    }
}

// ---------------- kernel 2: count queries per cell ----------------
__global__ void k_count_pts(const float* __restrict__ points) {
    const int b = blockIdx.y;
    const int p = blockIdx.x * blockDim.x + threadIdx.x;
    if (p >= NPTS) return;
    const float* pp = points + ((size_t)b * NPTS + p) * 3;
    float bx[9];
#pragma unroll
    for (int i = 0; i < 9; i++) bx[i] = g_box[b][i];
    atomicAdd(&g_pcnt[b][cell_of(pp[0], pp[1], pp[2], bx)], 1);
}

// ---------------- kernel 3: scan query counts -> cursors ----------------
__global__ void k_init_cursors() {
    const int b = blockIdx.x, tid = threadIdx.x;
    __shared__ int tot[256];
    int c0 = tid * CHUNK, s = 0;
    for (int j = 0; j < CHUNK; j++) { int c = c0 + j; if (c < NCELL) s += g_pcnt[b][c]; }
    tot[tid] = s;
    __syncthreads();
    if (tid == 0) { int run = 0; for (int i = 0; i < 256; i++) { int v = tot[i]; tot[i] = run; run += v; } }
    __syncthreads();
    int run = tot[tid];
    for (int j = 0; j < CHUNK; j++) { int c = c0 + j; if (c < NCELL) { g_pcur[b][c] = run; run += g_pcnt[b][c]; } }
}

// ---------------- kernel 4: scatter queries into cell-sorted order ----------------
__global__ void k_scatter_pts(const float* __restrict__ points) {
    const int b = blockIdx.y;
    const int p = blockIdx.x * blockDim.x + threadIdx.x;
    if (p >= NPTS) return;
    const float* pp = points + ((size_t)b * NPTS + p) * 3;
    float x = pp[0], y = pp[1], z = pp[2];
    float bx[9];
#pragma unroll
    for (int i = 0; i < 9; i++) bx[i] = g_box[b][i];
    int pos = atomicAdd(&g_pcur[b][cell_of(x, y, z, bx)], 1);
    g_pts[b][pos] = make_float4(x, y, z, __int_as_float(p));
}

// ---------------- kernel 5: main — r=0 start: count box -> box scan -> exact ball sweep ----------------
static constexpr int SM_MAIN = NSP * 16 + 16 * 4 + (NCELL + 1) * 2;  // 80066

__global__ __launch_bounds__(TMAIN, 2) void k_main(float* __restrict__ out) {
    extern __shared__ float smf[];
    float4* spk = (float4*)smf;                        // NSP float4
    float*  sbb = (float*)(spk + NSP);                 // 9 floats (+pad)
    unsigned short* cst = (unsigned short*)(sbb + 16); // NCELL+1

    const int b = blockIdx.y, tid = threadIdx.x;
    for (int i = tid; i < NSP; i += TMAIN) spk[i] = g_spk[b][i];
    for (int i = tid; i <= NCELL; i += TMAIN) cst[i] = g_cst[b][i];
    if (tid < 9) sbb[tid] = g_box[b][tid];
    __syncthreads();

    int t = blockIdx.x * TMAIN + tid;
    const bool valid = (t < NPTS);
    if (!valid) t = NPTS - 1;            // duplicate last point; harmless

    const float4 P = g_pts[b][t];
    const float px = P.x, py = P.y, pz = P.z;
    const int orig = __float_as_int(P.w);

    const float mnx = sbb[0], mny = sbb[1], mnz = sbb[2];
    const float hx = sbb[3], hy = sbb[4], hz = sbb[5];
    const float ihx = sbb[6], ihy = sbb[7], ihz = sbb[8];
    const int cx = min(G - 1, max(0, (int)((px - mnx) * ihx)));
    const int cy = min(G - 1, max(0, (int)((py - mny) * ihy)));
    const int cz = min(G - 1, max(0, (int)((pz - mnz) * ihz)));

    float bd[KNN];
    int   bo[KNN];   // key = (orig_site_idx << 12) | sorted_pos — lex order == jax tie-break
    auto insert = [&](float d, int kk) {
#pragma unroll
        for (int k = 0; k < KNN; k++) {
            const bool sw = (d < bd[k]) || ((d == bd[k]) && (kk < bo[k]));
            if (sw) {
                const float td = bd[k]; bd[k] = d;  d = td;
                const int   ti = bo[k]; bo[k] = kk; kk = ti;
            }
        }
    };
    auto scan_range = [&](int m, int m1) {
        for (; m + 2 <= m1; m += 2) {
            const float4 S0 = spk[m];
            const float4 S1 = spk[m + 1];
            const float dx0 = px - S0.x, dy0 = py - S0.y, dz0 = pz - S0.z;
            const float dx1 = px - S1.x, dy1 = py - S1.y, dz1 = pz - S1.z;
            const float d20 = fmaf(dz0, dz0, fmaf(dy0, dy0, dx0 * dx0));
            const float d21 = fmaf(dz1, dz1, fmaf(dy1, dy1, dx1 * dx1));
            if (d20 <= bd[KNN - 1]) insert(d20, __float_as_int(S0.w) | m);
            if (d21 <= bd[KNN - 1]) insert(d21, __float_as_int(S1.w) | (m + 1));
        }
        if (m < m1) {
            const float4 S = spk[m];
            const float dx = px - S.x, dy = py - S.y, dz = pz - S.z;
            const float d2 = fmaf(dz, dz, fmaf(dy, dy, dx * dx));
            if (d2 <= bd[KNN - 1]) insert(d2, __float_as_int(S.w) | m);
        }
    };

    // ---- Phase A: expand box around home cell until it holds >= 11 sites (counts only).
    //      Starts at r=0: in dense regions the home cell alone suffices.
    int bxl, bxh, byl, byh, bzl, bzh;
    for (int r = 0; ; r++) {
        bxl = max(cx - r, 0); bxh = min(cx + r, G - 1);
        byl = max(cy - r, 0); byh = min(cy + r, G - 1);
        bzl = max(cz - r, 0); bzh = min(cz + r, G - 1);
        int count = 0;
        for (int X = bxl; X <= bxh; X++) {
            const int rb = X * G;
            for (int Y = byl; Y <= byh; Y++) {
                const int base = (rb + Y) * G;
                count += (int)cst[base + bzh + 1] - (int)cst[base + bzl];
            }
        }
        if (count >= KNN) break;
        if (bxl == 0 && bxh == G - 1 && byl == 0 && byh == G - 1 &&
            bzl == 0 && bzh == G - 1) break;       // whole grid: count = NSP >= 11
    }

    // corner-distance upper bound on any box site's d2 (with fp slack) -> insert gate
    {
        const float fx = fmaxf(px - (mnx + (float)bxl * hx), (mnx + (float)(bxh + 1) * hx) - px);
        const float fy = fmaxf(py - (mny + (float)byl * hy), (mny + (float)(byh + 1) * hy) - py);
        const float fz = fmaxf(pz - (mnz + (float)bzl * hz), (mnz + (float)(bzh + 1) * hz) - pz);
        const float T = fmaf(fx, fx, fmaf(fy, fy, fz * fz)) * 1.0005f;
#pragma unroll
        for (int k = 0; k < KNN; k++) { bd[k] = T; bo[k] = SENT; }
    }

    // ---- Phase B: scan the box (contiguous z-strips). bd[10] becomes a REAL upper bound ----
    for (int X = bxl; X <= bxh; X++) {
        const int rb = X * G;
        for (int Y = byl; Y <= byh; Y++) {
            const int base = (rb + Y) * G;
            scan_range(cst[base + bzl], cst[base + bzh + 1]);
        }
    }

    // ---- Phase C: exact ball sweep: all cells intersecting ball(p, sqrt(bd10)), minus box ----
    {
        const float T2 = bd[KNN - 1] * 1.0005f;      // count>=11 => bd[10] is real
        const float sR = sqrtf(T2);
        const int qxl = min(G - 1, max(0, (int)((px - sR - mnx) * ihx)));
        const int qxh = min(G - 1, max(0, (int)((px + sR - mnx) * ihx)));
        const int qyl = min(G - 1, max(0, (int)((py - sR - mny) * ihy)));
        const int qyh = min(G - 1, max(0, (int)((py + sR - mny) * ihy)));

        for (int X = qxl; X <= qxh; X++) {
            const float lx = mnx + (float)X * hx;
            const float ax = fmaxf(0.0f, fmaxf(lx - px, px - (lx + hx)));
            const float ax2 = ax * ax;
            if (ax2 > bd[KNN - 1] * 1.0005f) continue;
            const bool inBx = (X >= bxl) && (X <= bxh);
            const int rb = X * G;
            for (int Y = qyl; Y <= qyh; Y++) {
                // dynamic gate: current bd[10] only shrinks; still an upper bound on true d2_11
                const float cur = bd[KNN - 1] * 1.0005f;
                const float ly = mny + (float)Y * hy;
                const float ay = fmaxf(0.0f, fmaxf(ly - py, py - (ly + hy)));
                const float dxy2 = fmaf(ay, ay, ax2);
                if (dxy2 > cur) continue;
                const float sq = sqrtf(fmaxf(cur - dxy2, 0.0f));
                int zlo = min(G - 1, max(0, (int)((pz - sq - mnz) * ihz)));
                int zhi = min(G - 1, max(0, (int)((pz + sq - mnz) * ihz)));
                const int base = (rb + Y) * G;
                if (inBx && Y >= byl && Y <= byh) {
                    // subtract already-scanned z interval [bzl, bzh]
                    const int z1h = min(zhi, bzl - 1);
                    if (zlo <= z1h) scan_range(cst[base + zlo], cst[base + z1h + 1]);
                    const int z2l = max(zlo, bzh + 1);
                    if (z2l <= zhi) scan_range(cst[base + z2l], cst[base + zhi + 1]);
                } else {
                    scan_range(cst[base + zlo], cst[base + zhi + 1]);
                }
            }
        }
    }

    // ---- Voronoi-edge epilogue on the 11 selected sites ----
    const int p0 = min(bo[0] & 4095, NSP - 1);
    const float4 C = spk[p0];
    const float tx = px - C.x, ty = py - C.y, tz = pz - C.z;
    float best = 3.4e38f;
#pragma unroll
    for (int j = 1; j < KNN; j++) {
        const int pj = min(bo[j] & 4095, NSP - 1);
        const float4 E = spk[pj];
        const float ex = E.x - C.x, ey = E.y - C.y, ez = E.z - C.z;
        const float el2 = fmaf(ez, ez, fmaf(ey, ey, ex * ex));
        const float dp  = fmaf(tz, ez, fmaf(ty, ey, tx * ex));
        const float tt  = fmaf(-0.5f, el2, dp) * rsqrtf(el2);  // (dp - el2/2)/sqrt(el2)
        best = fminf(best, tt * tt);
    }
    if (valid) out[(size_t)b * NPTS + orig] = best;
}

// ---------------- launch ----------------
extern "C" void kernel_launch(void* const* d_in, const int* in_sizes, int n_in,
                              void* d_out, int out_size)
{
    const float* points  = (const float*)d_in[0];
    const float* spoints = (const float*)d_in[1];
    float* out = (float*)d_out;

    cudaFuncSetAttribute(k_setup_sites, cudaFuncAttributeMaxDynamicSharedMemorySize, SM_SETUP);
    cudaFuncSetAttribute(k_main,        cudaFuncAttributeMaxDynamicSharedMemorySize, SM_MAIN);

    k_setup_sites<<<NB, 256, SM_SETUP>>>(spoints);
    dim3 gp((NPTS + 255) / 256, NB);
    k_count_pts<<<gp, 256>>>(points);
    k_init_cursors<<<NB, 256>>>();
    k_scatter_pts<<<gp, 256>>>(points);
    k_main<<<dim3(BLKS_MAIN, NB), TMAIN, SM_MAIN>>>(out);
}